// round 4
// baseline (speedup 1.0000x reference)
#include <cuda_runtime.h>
#include <cuda_bf16.h>
#include <math.h>
#include <stdint.h>

// ---------------- problem constants ----------------
#define LSEQ 2048
#define DMODEL 1024
#define NHEAD 16
#define HDIM 64
#define NLYR 4
#define WIN 256
#define IDIM 3280
#define KP2 3296          // IDIM padded to multiple of 32
#define VDIM 32000
#define EPSV 1e-5f

constexpr int WDD = NLYR * DMODEL * DMODEL;
constexpr int WID_ = NLYR * IDIM * DMODEL;
constexpr int WIDP = NLYR * DMODEL * KP2;   // padded w2
constexpr int WLM = VDIM * DMODEL;

// ---------------- scratch (static device globals) ----------------
__device__ float g_x[LSEQ * DMODEL];
__device__ float g_q[LSEQ * DMODEL];
__device__ float g_k[LSEQ * DMODEL];
__device__ float g_v[LSEQ * DMODEL];
__device__ float g_z1[LSEQ * IDIM];
__device__ float g_z3[LSEQ * IDIM];
__device__ __nv_bfloat16 g_xnh[LSEQ * DMODEL], g_xnl[LSEQ * DMODEL];
__device__ __nv_bfloat16 g_ah[LSEQ * DMODEL],  g_al[LSEQ * DMODEL];
__device__ __nv_bfloat16 g_mh[LSEQ * KP2],     g_ml[LSEQ * KP2];
__device__ __nv_bfloat16 g_wqh[WDD], g_wql[WDD];
__device__ __nv_bfloat16 g_wkh[WDD], g_wkl[WDD];
__device__ __nv_bfloat16 g_wvh[WDD], g_wvl[WDD];
__device__ __nv_bfloat16 g_woh[WDD], g_wol[WDD];
__device__ __nv_bfloat16 g_w1h[WID_], g_w1l[WID_];
__device__ __nv_bfloat16 g_w2h[WIDP], g_w2l[WIDP];
__device__ __nv_bfloat16 g_w3h[WID_], g_w3l[WID_];
__device__ __nv_bfloat16 g_lmh[WLM], g_lml[WLM];

// ---------------- PTX helpers (sm_80-class only; NO tcgen05) ----------------
__device__ __forceinline__ uint32_t smem_u32(const void* p) {
    uint32_t a;
    asm("{ .reg .u64 t; cvta.to.shared.u64 t, %1; cvt.u32.u64 %0, t; }" : "=r"(a) : "l"(p));
    return a;
}
__device__ __forceinline__ void ldmx4(uint32_t* r, uint32_t addr) {
    asm volatile("ldmatrix.sync.aligned.m8n8.x4.shared.b16 {%0,%1,%2,%3}, [%4];"
                 : "=r"(r[0]), "=r"(r[1]), "=r"(r[2]), "=r"(r[3]) : "r"(addr));
}
__device__ __forceinline__ void mma_bf16(float* c, const uint32_t* a, const uint32_t* b) {
    asm volatile(
        "mma.sync.aligned.m16n8k16.row.col.f32.bf16.bf16.f32 "
        "{%0,%1,%2,%3}, {%4,%5,%6,%7}, {%8,%9}, {%0,%1,%2,%3};"
        : "+f"(c[0]), "+f"(c[1]), "+f"(c[2]), "+f"(c[3])
        : "r"(a[0]), "r"(a[1]), "r"(a[2]), "r"(a[3]), "r"(b[0]), "r"(b[1]));
}
__device__ __forceinline__ void cpasync16(uint32_t dst, const void* src) {
    asm volatile("cp.async.cg.shared.global [%0], [%1], 16;" :: "r"(dst), "l"(src));
}
__device__ __forceinline__ void cpcommit() {
    asm volatile("cp.async.commit_group;" ::: "memory");
}

// ---------------- embedding gather ----------------
__global__ void embed_kernel(const int* __restrict__ tokens,
                             const float* __restrict__ ew,
                             float* __restrict__ x) {
    int i = blockIdx.x;
    int tok = tokens[i];
    const float4* src = (const float4*)(ew + (size_t)tok * DMODEL);
    float4* dst = (float4*)(x + (size_t)i * DMODEL);
    dst[threadIdx.x] = src[threadIdx.x];
}

// ---------------- fp32 -> bf16 hi/lo split conversion ----------------
__global__ void conv_hl_kernel(const float* __restrict__ s,
                               __nv_bfloat16* __restrict__ h,
                               __nv_bfloat16* __restrict__ l, int n) {
    int i = (blockIdx.x * blockDim.x + threadIdx.x) * 4;
    if (i < n) {
        float4 v = *(const float4*)(s + i);
        float vv[4] = {v.x, v.y, v.z, v.w};
        __nv_bfloat16 hh[4], ll[4];
#pragma unroll
        for (int t = 0; t < 4; t++) {
            hh[t] = __float2bfloat16(vv[t]);
            ll[t] = __float2bfloat16(vv[t] - __bfloat162float(hh[t]));
        }
        ((__nv_bfloat162*)(h + i))[0] = __halves2bfloat162(hh[0], hh[1]);
        ((__nv_bfloat162*)(h + i))[1] = __halves2bfloat162(hh[2], hh[3]);
        ((__nv_bfloat162*)(l + i))[0] = __halves2bfloat162(ll[0], ll[1]);
        ((__nv_bfloat162*)(l + i))[1] = __halves2bfloat162(ll[2], ll[3]);
    }
}

// conversion with K padding: src rows of IDIM -> dst rows of KP2 (pad = 0)
__global__ void conv_hl_pad_kernel(const float* __restrict__ s,
                                   __nv_bfloat16* __restrict__ h,
                                   __nv_bfloat16* __restrict__ l, int nrows) {
    int idx = blockIdx.x * blockDim.x + threadIdx.x;
    if (idx < nrows * KP2) {
        int row = idx / KP2;
        int col = idx - row * KP2;
        float v = (col < IDIM) ? s[(size_t)row * IDIM + col] : 0.f;
        __nv_bfloat16 hb = __float2bfloat16(v);
        h[idx] = hb;
        l[idx] = __float2bfloat16(v - __bfloat162float(hb));
    }
}

// ---------------- row RMSNorm (D=1024) -> bf16 hi/lo ----------------
__global__ void rmsnorm_kernel(const float* __restrict__ x,
                               const float* __restrict__ w,
                               __nv_bfloat16* __restrict__ yh,
                               __nv_bfloat16* __restrict__ yl) {
    const int row = blockIdx.x;
    const int t = threadIdx.x;
    const float* xr = x + (size_t)row * DMODEL;
    float v[4];
    float ss = 0.f;
#pragma unroll
    for (int j = 0; j < 4; j++) {
        float a = xr[t + j * 256];
        a = fminf(fmaxf(a, -10000.f), 10000.f);
        v[j] = a;
        ss = fmaf(a, a, ss);
    }
#pragma unroll
    for (int off = 16; off; off >>= 1) ss += __shfl_xor_sync(0xffffffffu, ss, off);
    __shared__ float red[8];
    if ((t & 31) == 0) red[t >> 5] = ss;
    __syncthreads();
    if (t < 32) {
        float s2 = (t < 8) ? red[t] : 0.f;
#pragma unroll
        for (int off = 4; off; off >>= 1) s2 += __shfl_xor_sync(0xffffffffu, s2, off);
        if (t == 0) red[0] = s2;
    }
    __syncthreads();
    float mean = red[0] * (1.f / DMODEL);
    float inv = 1.f / sqrtf(fmaxf(mean, EPSV) + EPSV);
#pragma unroll
    for (int j = 0; j < 4; j++) {
        int c = t + j * 256;
        float r = v[j] * inv * w[c];
        if (!isfinite(r)) r = 0.f;
        __nv_bfloat16 hb = __float2bfloat16(r);
        yh[(size_t)row * DMODEL + c] = hb;
        yl[(size_t)row * DMODEL + c] = __float2bfloat16(r - __bfloat162float(hb));
    }
}

// ---------------- per-head RMSNorm (64 dims), in place fp32 ----------------
__global__ void rmsnorm_head_kernel(float* __restrict__ q, const float* __restrict__ w) {
    int r = blockIdx.x * (blockDim.x >> 5) + (threadIdx.x >> 5);
    int lane = threadIdx.x & 31;
    float* p = q + (size_t)r * HDIM;
    float a0 = p[lane], a1 = p[lane + 32];
    a0 = fminf(fmaxf(a0, -10000.f), 10000.f);
    a1 = fminf(fmaxf(a1, -10000.f), 10000.f);
    float ss = a0 * a0 + a1 * a1;
#pragma unroll
    for (int off = 16; off; off >>= 1) ss += __shfl_xor_sync(0xffffffffu, ss, off);
    float mean = ss * (1.f / HDIM);
    float inv = 1.f / sqrtf(fmaxf(mean, EPSV) + EPSV);
    float r0 = a0 * inv * w[lane];
    float r1 = a1 * inv * w[lane + 32];
    if (!isfinite(r0)) r0 = 0.f;
    if (!isfinite(r1)) r1 = 0.f;
    p[lane] = r0;
    p[lane + 32] = r1;
}

// ---------------- flash-style sliding-window attention (fp32) ----------------
#define QT 32
__global__ void __launch_bounds__(256)
attn2_kernel(const float* __restrict__ q, const float* __restrict__ k,
             const float* __restrict__ v,
             __nv_bfloat16* __restrict__ oh, __nv_bfloat16* __restrict__ ol) {
    const int h = blockIdx.y;
    const int qt = blockIdx.x * QT;
    const int tid = threadIdx.x;
    const int r = tid >> 3;
    const int g = tid & 7;
    const int i = qt + r;

    __shared__ float Qs[QT][65];
    __shared__ float Kt[64][36];
    __shared__ float Vs[QT][68];
    __shared__ float Ps[QT][33];

    {
        const float* qp = q + (size_t)i * DMODEL + h * HDIM + g * 8;
#pragma unroll
        for (int t2 = 0; t2 < 8; t2++) Qs[r][g * 8 + t2] = qp[t2];
    }

    float m = -INFINITY, lsum = 0.f;
    float acc[8];
#pragma unroll
    for (int d = 0; d < 8; d++) acc[d] = 0.f;

    int cs = max(0, qt - (WIN - 1)) & ~31;
    for (int jc = cs; jc <= qt + QT - 1; jc += 32) {
        __syncthreads();
        {
            const int row = tid >> 3;
            const int c0 = (tid & 7) * 8;
            const float* kp = k + (size_t)(jc + row) * DMODEL + h * HDIM + c0;
            const float* vp = v + (size_t)(jc + row) * DMODEL + h * HDIM + c0;
            float4 k0 = *(const float4*)kp;
            float4 k1 = *(const float4*)(kp + 4);
            Kt[c0 + 0][row] = k0.x; Kt[c0 + 1][row] = k0.y;
            Kt[c0 + 2][row] = k0.z; Kt[c0 + 3][row] = k0.w;
            Kt[c0 + 4][row] = k1.x; Kt[c0 + 5][row] = k1.y;
            Kt[c0 + 6][row] = k1.z; Kt[c0 + 7][row] = k1.w;
            *(float4*)&Vs[row][c0] = *(const float4*)vp;
            *(float4*)&Vs[row][c0 + 4] = *(const float4*)(vp + 4);
        }
        __syncthreads();

        float s0 = 0.f, s1 = 0.f, s2 = 0.f, s3 = 0.f;
#pragma unroll
        for (int d = 0; d < 64; d++) {
            float4 kd = *(const float4*)&Kt[d][g * 4];
            float qd = Qs[r][d];
            s0 = fmaf(qd, kd.x, s0);
            s1 = fmaf(qd, kd.y, s1);
            s2 = fmaf(qd, kd.z, s2);
            s3 = fmaf(qd, kd.w, s3);
        }
        const int jb = jc + g * 4;
        s0 = ((jb + 0) <= i && (i - (jb + 0)) < WIN) ? s0 * 0.125f : -INFINITY;
        s1 = ((jb + 1) <= i && (i - (jb + 1)) < WIN) ? s1 * 0.125f : -INFINITY;
        s2 = ((jb + 2) <= i && (i - (jb + 2)) < WIN) ? s2 * 0.125f : -INFINITY;
        s3 = ((jb + 3) <= i && (i - (jb + 3)) < WIN) ? s3 * 0.125f : -INFINITY;

        float mc = fmaxf(fmaxf(s0, s1), fmaxf(s2, s3));
        mc = fmaxf(mc, __shfl_xor_sync(0xffffffffu, mc, 1));
        mc = fmaxf(mc, __shfl_xor_sync(0xffffffffu, mc, 2));
        mc = fmaxf(mc, __shfl_xor_sync(0xffffffffu, mc, 4));
        float mnew = fmaxf(m, mc);

        float alpha = 1.f;
        float p0 = 0.f, p1 = 0.f, p2 = 0.f, p3 = 0.f;
        if (mnew != -INFINITY) {
            alpha = (m == -INFINITY) ? 0.f : expf(m - mnew);
            p0 = expf(s0 - mnew);
            p1 = expf(s1 - mnew);
            p2 = expf(s2 - mnew);
            p3 = expf(s3 - mnew);
            m = mnew;
        }
        Ps[r][g * 4 + 0] = p0;
        Ps[r][g * 4 + 1] = p1;
        Ps[r][g * 4 + 2] = p2;
        Ps[r][g * 4 + 3] = p3;
        lsum = lsum * alpha + (p0 + p1 + p2 + p3);
        __syncwarp();

#pragma unroll
        for (int d = 0; d < 8; d++) acc[d] *= alpha;
#pragma unroll 4
        for (int j = 0; j < 32; j++) {
            float p = Ps[r][j];
            float4 v0 = *(const float4*)&Vs[j][g * 8];
            float4 v1 = *(const float4*)&Vs[j][g * 8 + 4];
            acc[0] = fmaf(p, v0.x, acc[0]);
            acc[1] = fmaf(p, v0.y, acc[1]);
            acc[2] = fmaf(p, v0.z, acc[2]);
            acc[3] = fmaf(p, v0.w, acc[3]);
            acc[4] = fmaf(p, v1.x, acc[4]);
            acc[5] = fmaf(p, v1.y, acc[5]);
            acc[6] = fmaf(p, v1.z, acc[6]);
            acc[7] = fmaf(p, v1.w, acc[7]);
        }
    }

    float lt = lsum;
    lt += __shfl_xor_sync(0xffffffffu, lt, 1);
    lt += __shfl_xor_sync(0xffffffffu, lt, 2);
    lt += __shfl_xor_sync(0xffffffffu, lt, 4);
    float invl = 1.f / lt;
    size_t ob = (size_t)i * DMODEL + h * HDIM + g * 8;
#pragma unroll
    for (int d = 0; d < 8; d++) {
        float rv = acc[d] * invl;
        if (!isfinite(rv)) rv = 0.f;
        __nv_bfloat16 hb = __float2bfloat16(rv);
        oh[ob + d] = hb;
        ol[ob + d] = __float2bfloat16(rv - __bfloat162float(hb));
    }
}

// ---------------- SwiGLU elementwise -> bf16 hi/lo (padded rows) ----------------
__global__ void swiglu_kernel(const float* __restrict__ z1, const float* __restrict__ z3,
                              __nv_bfloat16* __restrict__ mh, __nv_bfloat16* __restrict__ ml) {
    int idx = blockIdx.x * blockDim.x + threadIdx.x;
    if (idx < LSEQ * KP2) {
        int row = idx / KP2;
        int col = idx - row * KP2;
        float s = 0.f;
        if (col < IDIM) {
            float a = z1[(size_t)row * IDIM + col];
            float b = z3[(size_t)row * IDIM + col];
            s = (a / (1.f + expf(-a))) * b;
        }
        __nv_bfloat16 hb = __float2bfloat16(s);
        mh[idx] = hb;
        ml[idx] = __float2bfloat16(s - __bfloat162float(hb));
    }
}

// ---------------- bf16 split GEMM via mma.sync + cp.async 4-stage pipeline ----
// C[m,n] = sum_k A[m,k]*B[n,k] + bias[n];  A = Ah+Al, B = Bh+Bl
// 3 passes (Ah*Bh + Ah*Bl + Al*Bh) into shared fp32 accumulators.
// MODE 0: store, 1: C +=, 2: clip +-50
#define ROWB 80                    // 40 bf16 per smem row (32 data + 8 pad)
#define TILEB (128 * ROWB)         // 10240 bytes per tile
#define NST 4
#define GSMEM (NST * 4 * TILEB)    // 163840 bytes

template <int MODE>
__global__ void __launch_bounds__(256, 1)
bgemm_kernel(const __nv_bfloat16* __restrict__ Ah, const __nv_bfloat16* __restrict__ Al,
             const __nv_bfloat16* __restrict__ Bh0, const __nv_bfloat16* __restrict__ Bl0,
             const __nv_bfloat16* __restrict__ Bh1, const __nv_bfloat16* __restrict__ Bl1,
             const __nv_bfloat16* __restrict__ Bh2, const __nv_bfloat16* __restrict__ Bl2,
             const float* __restrict__ b0, const float* __restrict__ b1,
             const float* __restrict__ b2,
             float* __restrict__ C0, float* __restrict__ C1, float* __restrict__ C2,
             int M, int N, int K) {
    const __nv_bfloat16* Bh = (blockIdx.z == 0) ? Bh0 : (blockIdx.z == 1 ? Bh1 : Bh2);
    const __nv_bfloat16* Bl = (blockIdx.z == 0) ? Bl0 : (blockIdx.z == 1 ? Bl1 : Bl2);
    const float* bias = (blockIdx.z == 0) ? b0 : (blockIdx.z == 1 ? b1 : b2);
    float* C = (blockIdx.z == 0) ? C0 : (blockIdx.z == 1 ? C1 : C2);

    extern __shared__ char smem[];
    const uint32_t sb = smem_u32(smem);
    const int tid = threadIdx.x;
    const int wid = tid >> 5;
    const int lane = tid & 31;
    const int bm = blockIdx.y * 128;
    const int bn = blockIdx.x * 128;

    // ---- staging setup: thread group tgrp handles one of {Ah, Al, Bh, Bl} ----
    const int tgrp = tid >> 6;       // 0..3
    const int tl = tid & 63;
    const int row0 = tl >> 2;        // base row (0..15), +16 per step
    const int ch = tl & 3;           // 16B chunk within row
    const bool isB = tgrp >= 2;
    const __nv_bfloat16* gbase =
        (tgrp == 0) ? Ah : (tgrp == 1) ? Al : (tgrp == 2) ? Bh : Bl;

    const __nv_bfloat16* srcp[8];
#pragma unroll
    for (int c2 = 0; c2 < 8; c2++) {
        int row = row0 + c2 * 16;
        int grow = isB ? min(bn + row, N - 1) : (bm + row);
        srcp[c2] = gbase + (size_t)grow * K + ch * 8;
    }
    const uint32_t dgrp = sb + (uint32_t)tgrp * TILEB + (uint32_t)ch * 16;

    // ---- fragment accumulators ----
    float acc[4][4][4];
#pragma unroll
    for (int a = 0; a < 4; a++)
#pragma unroll
        for (int b = 0; b < 4; b++)
#pragma unroll
            for (int c = 0; c < 4; c++) acc[a][b][c] = 0.f;

    const int wm = (wid & 1) * 64;
    const int wn = (wid >> 1) * 32;
    const int lrow = lane & 15;
    const int lcol = lane >> 4;
    // byte offsets inside a tile for ldmatrix
    const uint32_t offA = (uint32_t)(wm + lrow) * ROWB + (uint32_t)lcol * 16;
    const uint32_t offB = (uint32_t)(wn + lrow) * ROWB + (uint32_t)lcol * 16;

    const int NC = K >> 5;   // K multiple of 32 guaranteed

    // ---- prefetch stages 0..NST-2 ----
#pragma unroll
    for (int s = 0; s < NST - 1; s++) {
        const uint32_t db = dgrp + (uint32_t)(s * 4) * TILEB;
        const int kc = s * 32;
#pragma unroll
        for (int c2 = 0; c2 < 8; c2++)
            cpasync16(db + (uint32_t)(row0 + c2 * 16) * ROWB, srcp[c2] + kc);
        cpcommit();
    }

    for (int c = 0; c < NC; c++) {
        asm volatile("cp.async.wait_group 2;" ::: "memory");
        __syncthreads();

        const uint32_t tb = sb + (uint32_t)((c % NST) * 4) * TILEB;
#pragma unroll
        for (int ks = 0; ks < 2; ks++) {
            const uint32_t ko = (uint32_t)ks * 32;
            uint32_t bh[4][2], bl[4][2];
#pragma unroll
            for (int p = 0; p < 2; p++) {
                uint32_t qq[4];
                ldmx4(qq, tb + 2 * TILEB + offB + (uint32_t)p * (16 * ROWB) + ko);
                bh[2 * p][0] = qq[0]; bh[2 * p][1] = qq[2];
                bh[2 * p + 1][0] = qq[1]; bh[2 * p + 1][1] = qq[3];
                ldmx4(qq, tb + 3 * TILEB + offB + (uint32_t)p * (16 * ROWB) + ko);
                bl[2 * p][0] = qq[0]; bl[2 * p][1] = qq[2];
                bl[2 * p + 1][0] = qq[1]; bl[2 * p + 1][1] = qq[3];
            }
#pragma unroll
            for (int mi = 0; mi < 4; mi++) {
                uint32_t ah[4], al[4];
                ldmx4(ah, tb + offA + (uint32_t)mi * (16 * ROWB) + ko);
                ldmx4(al, tb + TILEB + offA + (uint32_t)mi * (16 * ROWB) + ko);
#pragma unroll
                for (int ni = 0; ni < 4; ni++) mma_bf16(acc[mi][ni], ah, bh[ni]);
#pragma unroll
                for (int ni = 0; ni < 4; ni++) mma_bf16(acc[mi][ni], ah, bl[ni]);
#pragma unroll
                for (int ni = 0; ni < 4; ni++) mma_bf16(acc[mi][ni], al, bh[ni]);
            }
        }
        __syncthreads();

        const int nc = c + NST - 1;
        if (nc < NC) {
            const uint32_t db = dgrp + (uint32_t)((nc % NST) * 4) * TILEB;
            const int kc = nc * 32;
#pragma unroll
            for (int c2 = 0; c2 < 8; c2++)
                cpasync16(db + (uint32_t)(row0 + c2 * 16) * ROWB, srcp[c2] + kc);
        }
        cpcommit();
    }

    // ---- epilogue ----
#pragma unroll
    for (int mi = 0; mi < 4; mi++) {
        const int r0 = bm + wm + mi * 16 + (lane >> 2);
#pragma unroll
        for (int ni = 0; ni < 4; ni++) {
            const int c0 = bn + wn + ni * 8 + (lane & 3) * 2;
            if (c0 < N) {
                const float bv0 = bias[c0];
                const float bv1 = bias[c0 + 1];
                float* p0 = C + (size_t)r0 * N + c0;
                float* p1 = C + (size_t)(r0 + 8) * N + c0;
                float v00 = acc[mi][ni][0] + bv0;
                float v01 = acc[mi][ni][1] + bv1;
                float v10 = acc[mi][ni][2] + bv0;
                float v11 = acc[mi][ni][3] + bv1;
                if (MODE == 1) {
                    v00 += p0[0]; v01 += p0[1];
                    v10 += p1[0]; v11 += p1[1];
                }
                if (MODE == 2) {
                    v00 = fminf(fmaxf(v00, -50.f), 50.f);
                    v01 = fminf(fmaxf(v01, -50.f), 50.f);
                    v10 = fminf(fmaxf(v10, -50.f), 50.f);
                    v11 = fminf(fmaxf(v11, -50.f), 50.f);
                }
                p0[0] = v00; p0[1] = v01;
                p1[0] = v10; p1[1] = v11;
            }
        }
    }
}

template <int MODE>
static void launch_bgemm(const __nv_bfloat16* Ah, const __nv_bfloat16* Al,
                         const __nv_bfloat16* Bh0, const __nv_bfloat16* Bl0,
                         const __nv_bfloat16* Bh1, const __nv_bfloat16* Bl1,
                         const __nv_bfloat16* Bh2, const __nv_bfloat16* Bl2,
                         const float* b0, const float* b1, const float* b2,
                         float* C0, float* C1, float* C2,
                         int M, int N, int K, int nz) {
    cudaFuncSetAttribute(bgemm_kernel<MODE>, cudaFuncAttributeMaxDynamicSharedMemorySize,
                         GSMEM);
    dim3 grid((N + 127) / 128, M / 128, nz);
    bgemm_kernel<MODE><<<grid, 256, GSMEM>>>(Ah, Al, Bh0, Bl0, Bh1, Bl1, Bh2, Bl2,
                                             b0, b1, b2, C0, C1, C2, M, N, K);
}

// ---------------- driver ----------------
extern "C" void kernel_launch(void* const* d_in, const int* in_sizes, int n_in,
                              void* d_out, int out_size) {
    const int*   tokens  = (const int*)d_in[0];
    const float* embed_w = (const float*)d_in[1];
    const float* ln1_w   = (const float*)d_in[2];
    const float* ln2_w   = (const float*)d_in[3];
    const float* wq_w    = (const float*)d_in[4];
    const float* wq_b    = (const float*)d_in[5];
    const float* wk_w    = (const float*)d_in[6];
    const float* wk_b    = (const float*)d_in[7];
    const float* wv_w    = (const float*)d_in[8];
    const float* wv_b    = (const float*)d_in[9];
    const float* wo_w    = (const float*)d_in[10];
    const float* wo_b    = (const float*)d_in[11];
    const float* qn_w    = (const float*)d_in[12];
    const float* kn_w    = (const float*)d_in[13];
    const float* w1_w    = (const float*)d_in[14];
    const float* w1_b    = (const float*)d_in[15];
    const float* w2_w    = (const float*)d_in[16];
    const float* w2_b    = (const float*)d_in[17];
    const float* w3_w    = (const float*)d_in[18];
    const float* w3_b    = (const float*)d_in[19];
    const float* lnf_w   = (const float*)d_in[20];
    const float* lm_w    = (const float*)d_in[21];
    const float* lm_b    = (const float*)d_in[22];
    float* out = (float*)d_out;

    float *x, *q, *k, *v, *z1, *z3;
    __nv_bfloat16 *xnh, *xnl, *ah, *al, *mh, *ml;
    __nv_bfloat16 *wqh, *wql, *wkh, *wkl, *wvh, *wvl, *woh, *wol;
    __nv_bfloat16 *w1h, *w1l, *w2h, *w2l, *w3h, *w3l, *lmh, *lml;
    cudaGetSymbolAddress((void**)&x, g_x);
    cudaGetSymbolAddress((void**)&q, g_q);
    cudaGetSymbolAddress((void**)&k, g_k);
    cudaGetSymbolAddress((void**)&v, g_v);
    cudaGetSymbolAddress((void**)&z1, g_z1);
    cudaGetSymbolAddress((void**)&z3, g_z3);
    cudaGetSymbolAddress((void**)&xnh, g_xnh);
    cudaGetSymbolAddress((void**)&xnl, g_xnl);
    cudaGetSymbolAddress((void**)&ah, g_ah);
    cudaGetSymbolAddress((void**)&al, g_al);
    cudaGetSymbolAddress((void**)&mh, g_mh);
    cudaGetSymbolAddress((void**)&ml, g_ml);
    cudaGetSymbolAddress((void**)&wqh, g_wqh);
    cudaGetSymbolAddress((void**)&wql, g_wql);
    cudaGetSymbolAddress((void**)&wkh, g_wkh);
    cudaGetSymbolAddress((void**)&wkl, g_wkl);
    cudaGetSymbolAddress((void**)&wvh, g_wvh);
    cudaGetSymbolAddress((void**)&wvl, g_wvl);
    cudaGetSymbolAddress((void**)&woh, g_woh);
    cudaGetSymbolAddress((void**)&wol, g_wol);
    cudaGetSymbolAddress((void**)&w1h, g_w1h);
    cudaGetSymbolAddress((void**)&w1l, g_w1l);
    cudaGetSymbolAddress((void**)&w2h, g_w2h);
    cudaGetSymbolAddress((void**)&w2l, g_w2l);
    cudaGetSymbolAddress((void**)&w3h, g_w3h);
    cudaGetSymbolAddress((void**)&w3l, g_w3l);
    cudaGetSymbolAddress((void**)&lmh, g_lmh);
    cudaGetSymbolAddress((void**)&lml, g_lml);

    // weight split conversions (w2 gets K-padded layout)
    const int CB = 256;
    conv_hl_kernel<<<(WDD / 4 + CB - 1) / CB, CB>>>(wq_w, wqh, wql, WDD);
    conv_hl_kernel<<<(WDD / 4 + CB - 1) / CB, CB>>>(wk_w, wkh, wkl, WDD);
    conv_hl_kernel<<<(WDD / 4 + CB - 1) / CB, CB>>>(wv_w, wvh, wvl, WDD);
    conv_hl_kernel<<<(WDD / 4 + CB - 1) / CB, CB>>>(wo_w, woh, wol, WDD);
    conv_hl_kernel<<<(WID_ / 4 + CB - 1) / CB, CB>>>(w1_w, w1h, w1l, WID_);
    conv_hl_kernel<<<(WID_ / 4 + CB - 1) / CB, CB>>>(w3_w, w3h, w3l, WID_);
    conv_hl_pad_kernel<<<(WIDP + CB - 1) / CB, CB>>>(w2_w, w2h, w2l, NLYR * DMODEL);
    conv_hl_kernel<<<(WLM / 4 + CB - 1) / CB, CB>>>(lm_w, lmh, lml, WLM);

    embed_kernel<<<LSEQ, 256>>>(tokens, embed_w, x);

    for (int l = 0; l < NLYR; l++) {
        const size_t dd = (size_t)l * DMODEL * DMODEL;
        const size_t db = (size_t)l * DMODEL;
        const size_t di = (size_t)l * IDIM * DMODEL;
        const size_t dip = (size_t)l * DMODEL * KP2;
        const size_t dib = (size_t)l * IDIM;

        rmsnorm_kernel<<<LSEQ, 256>>>(x, ln1_w + db, xnh, xnl);
        launch_bgemm<0>(xnh, xnl,
                        wqh + dd, wql + dd, wkh + dd, wkl + dd, wvh + dd, wvl + dd,
                        wq_b + db, wk_b + db, wv_b + db,
                        q, k, v, LSEQ, DMODEL, DMODEL, 3);
        rmsnorm_head_kernel<<<(LSEQ * NHEAD) / 8, 256>>>(q, qn_w + (size_t)l * HDIM);
        rmsnorm_head_kernel<<<(LSEQ * NHEAD) / 8, 256>>>(k, kn_w + (size_t)l * HDIM);
        attn2_kernel<<<dim3(LSEQ / QT, NHEAD), 256>>>(q, k, v, ah, al);
        launch_bgemm<1>(ah, al,
                        woh + dd, wol + dd, woh + dd, wol + dd, woh + dd, wol + dd,
                        wo_b + db, wo_b + db, wo_b + db,
                        x, x, x, LSEQ, DMODEL, DMODEL, 1);

        rmsnorm_kernel<<<LSEQ, 256>>>(x, ln2_w + db, xnh, xnl);
        launch_bgemm<0>(xnh, xnl,
                        w1h + di, w1l + di, w3h + di, w3l + di, w3h + di, w3l + di,
                        w1_b + dib, w3_b + dib, w3_b + dib,
                        z1, z3, z3, LSEQ, IDIM, DMODEL, 2);
        swiglu_kernel<<<(LSEQ * KP2 + 255) / 256, 256>>>(z1, z3, mh, ml);
        launch_bgemm<1>(mh, ml,
                        w2h + dip, w2l + dip, w2h + dip, w2l + dip, w2h + dip, w2l + dip,
                        w2_b + db, w2_b + db, w2_b + db,
                        x, x, x, LSEQ, DMODEL, KP2, 1);
    }

    rmsnorm_kernel<<<LSEQ, 256>>>(x, lnf_w, xnh, xnl);
    launch_bgemm<2>(xnh, xnl,
                    lmh, lml, lmh, lml, lmh, lml,
                    lm_b, lm_b, lm_b,
                    out, out, out, LSEQ, VDIM, DMODEL, 1);
}

// round 5
// speedup vs baseline: 1.0783x; 1.0783x over previous
#include <cuda_runtime.h>
#include <cuda_bf16.h>
#include <math.h>
#include <stdint.h>

// ---------------- problem constants ----------------
#define LSEQ 2048
#define DMODEL 1024
#define NHEAD 16
#define HDIM 64
#define NLYR 4
#define WIN 256
#define IDIM 3280
#define KP2 3296          // IDIM padded to multiple of 32
#define VDIM 32000
#define EPSV 1e-5f

constexpr int WDD = NLYR * DMODEL * DMODEL;
constexpr int WID_ = NLYR * IDIM * DMODEL;
constexpr int WIDP = NLYR * DMODEL * KP2;   // padded w2
constexpr int WLM = VDIM * DMODEL;

// ---------------- scratch (static device globals) ----------------
__device__ float g_x[LSEQ * DMODEL];
__device__ float g_q[LSEQ * DMODEL];
__device__ float g_k[LSEQ * DMODEL];
__device__ float g_v[LSEQ * DMODEL];
__device__ float g_z1[LSEQ * IDIM];
__device__ float g_z3[LSEQ * IDIM];
__device__ __nv_bfloat16 g_xnh[LSEQ * DMODEL], g_xnl[LSEQ * DMODEL];
__device__ __nv_bfloat16 g_ah[LSEQ * DMODEL],  g_al[LSEQ * DMODEL];
__device__ __nv_bfloat16 g_mh[LSEQ * KP2],     g_ml[LSEQ * KP2];
__device__ __nv_bfloat16 g_wqh[WDD], g_wql[WDD];
__device__ __nv_bfloat16 g_wkh[WDD], g_wkl[WDD];
__device__ __nv_bfloat16 g_wvh[WDD], g_wvl[WDD];
__device__ __nv_bfloat16 g_woh[WDD], g_wol[WDD];
__device__ __nv_bfloat16 g_w1h[WID_], g_w1l[WID_];
__device__ __nv_bfloat16 g_w2h[WIDP], g_w2l[WIDP];
__device__ __nv_bfloat16 g_w3h[WID_], g_w3l[WID_];
__device__ __nv_bfloat16 g_lmh[WLM], g_lml[WLM];

// ---------------- PTX helpers (sm_80-class only; NO tcgen05) ----------------
__device__ __forceinline__ uint32_t smem_u32(const void* p) {
    uint32_t a;
    asm("{ .reg .u64 t; cvta.to.shared.u64 t, %1; cvt.u32.u64 %0, t; }" : "=r"(a) : "l"(p));
    return a;
}
__device__ __forceinline__ void ldmx4(uint32_t* r, uint32_t addr) {
    asm volatile("ldmatrix.sync.aligned.m8n8.x4.shared.b16 {%0,%1,%2,%3}, [%4];"
                 : "=r"(r[0]), "=r"(r[1]), "=r"(r[2]), "=r"(r[3]) : "r"(addr));
}
__device__ __forceinline__ void mma_bf16(float* c, const uint32_t* a, const uint32_t* b) {
    asm volatile(
        "mma.sync.aligned.m16n8k16.row.col.f32.bf16.bf16.f32 "
        "{%0,%1,%2,%3}, {%4,%5,%6,%7}, {%8,%9}, {%0,%1,%2,%3};"
        : "+f"(c[0]), "+f"(c[1]), "+f"(c[2]), "+f"(c[3])
        : "r"(a[0]), "r"(a[1]), "r"(a[2]), "r"(a[3]), "r"(b[0]), "r"(b[1]));
}
__device__ __forceinline__ void cpasync16(uint32_t dst, const void* src) {
    asm volatile("cp.async.cg.shared.global [%0], [%1], 16;" :: "r"(dst), "l"(src));
}
__device__ __forceinline__ void cpcommit() {
    asm volatile("cp.async.commit_group;" ::: "memory");
}

// ---------------- embedding gather ----------------
__global__ void embed_kernel(const int* __restrict__ tokens,
                             const float* __restrict__ ew,
                             float* __restrict__ x) {
    int i = blockIdx.x;
    int tok = tokens[i];
    const float4* src = (const float4*)(ew + (size_t)tok * DMODEL);
    float4* dst = (float4*)(x + (size_t)i * DMODEL);
    dst[threadIdx.x] = src[threadIdx.x];
}

// ---------------- fp32 -> bf16 hi/lo split conversion ----------------
__global__ void conv_hl_kernel(const float* __restrict__ s,
                               __nv_bfloat16* __restrict__ h,
                               __nv_bfloat16* __restrict__ l, int n) {
    int i = (blockIdx.x * blockDim.x + threadIdx.x) * 4;
    if (i < n) {
        float4 v = *(const float4*)(s + i);
        float vv[4] = {v.x, v.y, v.z, v.w};
        __nv_bfloat16 hh[4], ll[4];
#pragma unroll
        for (int t = 0; t < 4; t++) {
            hh[t] = __float2bfloat16(vv[t]);
            ll[t] = __float2bfloat16(vv[t] - __bfloat162float(hh[t]));
        }
        ((__nv_bfloat162*)(h + i))[0] = __halves2bfloat162(hh[0], hh[1]);
        ((__nv_bfloat162*)(h + i))[1] = __halves2bfloat162(hh[2], hh[3]);
        ((__nv_bfloat162*)(l + i))[0] = __halves2bfloat162(ll[0], ll[1]);
        ((__nv_bfloat162*)(l + i))[1] = __halves2bfloat162(ll[2], ll[3]);
    }
}

// conversion with K padding: src rows of IDIM -> dst rows of KP2 (pad = 0)
__global__ void conv_hl_pad_kernel(const float* __restrict__ s,
                                   __nv_bfloat16* __restrict__ h,
                                   __nv_bfloat16* __restrict__ l, int nrows) {
    int idx = blockIdx.x * blockDim.x + threadIdx.x;
    if (idx < nrows * KP2) {
        int row = idx / KP2;
        int col = idx - row * KP2;
        float v = (col < IDIM) ? s[(size_t)row * IDIM + col] : 0.f;
        __nv_bfloat16 hb = __float2bfloat16(v);
        h[idx] = hb;
        l[idx] = __float2bfloat16(v - __bfloat162float(hb));
    }
}

// ---------------- row RMSNorm (D=1024) -> bf16 hi/lo ----------------
__global__ void rmsnorm_kernel(const float* __restrict__ x,
                               const float* __restrict__ w,
                               __nv_bfloat16* __restrict__ yh,
                               __nv_bfloat16* __restrict__ yl) {
    const int row = blockIdx.x;
    const int t = threadIdx.x;
    const float* xr = x + (size_t)row * DMODEL;
    float v[4];
    float ss = 0.f;
#pragma unroll
    for (int j = 0; j < 4; j++) {
        float a = xr[t + j * 256];
        a = fminf(fmaxf(a, -10000.f), 10000.f);
        v[j] = a;
        ss = fmaf(a, a, ss);
    }
#pragma unroll
    for (int off = 16; off; off >>= 1) ss += __shfl_xor_sync(0xffffffffu, ss, off);
    __shared__ float red[8];
    if ((t & 31) == 0) red[t >> 5] = ss;
    __syncthreads();
    if (t < 32) {
        float s2 = (t < 8) ? red[t] : 0.f;
#pragma unroll
        for (int off = 4; off; off >>= 1) s2 += __shfl_xor_sync(0xffffffffu, s2, off);
        if (t == 0) red[0] = s2;
    }
    __syncthreads();
    float mean = red[0] * (1.f / DMODEL);
    float inv = 1.f / sqrtf(fmaxf(mean, EPSV) + EPSV);
#pragma unroll
    for (int j = 0; j < 4; j++) {
        int c = t + j * 256;
        float r = v[j] * inv * w[c];
        if (!isfinite(r)) r = 0.f;
        __nv_bfloat16 hb = __float2bfloat16(r);
        yh[(size_t)row * DMODEL + c] = hb;
        yl[(size_t)row * DMODEL + c] = __float2bfloat16(r - __bfloat162float(hb));
    }
}

// ---------------- per-head RMSNorm for q AND k in one launch ----------------
__global__ void rmsnorm_head2_kernel(float* __restrict__ q, float* __restrict__ k,
                                     const float* __restrict__ qw,
                                     const float* __restrict__ kw) {
    float* p0 = blockIdx.y ? k : q;
    const float* w = blockIdx.y ? kw : qw;
    int r = blockIdx.x * (blockDim.x >> 5) + (threadIdx.x >> 5);
    int lane = threadIdx.x & 31;
    float* p = p0 + (size_t)r * HDIM;
    float a0 = p[lane], a1 = p[lane + 32];
    a0 = fminf(fmaxf(a0, -10000.f), 10000.f);
    a1 = fminf(fmaxf(a1, -10000.f), 10000.f);
    float ss = a0 * a0 + a1 * a1;
#pragma unroll
    for (int off = 16; off; off >>= 1) ss += __shfl_xor_sync(0xffffffffu, ss, off);
    float mean = ss * (1.f / HDIM);
    float inv = 1.f / sqrtf(fmaxf(mean, EPSV) + EPSV);
    float r0 = a0 * inv * w[lane];
    float r1 = a1 * inv * w[lane + 32];
    if (!isfinite(r0)) r0 = 0.f;
    if (!isfinite(r1)) r1 = 0.f;
    p[lane] = r0;
    p[lane + 32] = r1;
}

// ---------------- flash-style sliding-window attention (fp32) ----------------
#define QT 32
__global__ void __launch_bounds__(256)
attn2_kernel(const float* __restrict__ q, const float* __restrict__ k,
             const float* __restrict__ v,
             __nv_bfloat16* __restrict__ oh, __nv_bfloat16* __restrict__ ol) {
    const int h = blockIdx.y;
    const int qt = blockIdx.x * QT;
    const int tid = threadIdx.x;
    const int r = tid >> 3;
    const int g = tid & 7;
    const int i = qt + r;

    __shared__ float Qs[QT][65];
    __shared__ float Kt[64][36];
    __shared__ float Vs[QT][68];
    __shared__ float Ps[QT][33];

    {
        const float* qp = q + (size_t)i * DMODEL + h * HDIM + g * 8;
#pragma unroll
        for (int t2 = 0; t2 < 8; t2++) Qs[r][g * 8 + t2] = qp[t2];
    }

    float m = -INFINITY, lsum = 0.f;
    float acc[8];
#pragma unroll
    for (int d = 0; d < 8; d++) acc[d] = 0.f;

    int cs = max(0, qt - (WIN - 1)) & ~31;
    for (int jc = cs; jc <= qt + QT - 1; jc += 32) {
        __syncthreads();
        {
            const int row = tid >> 3;
            const int c0 = (tid & 7) * 8;
            const float* kp = k + (size_t)(jc + row) * DMODEL + h * HDIM + c0;
            const float* vp = v + (size_t)(jc + row) * DMODEL + h * HDIM + c0;
            float4 k0 = *(const float4*)kp;
            float4 k1 = *(const float4*)(kp + 4);
            Kt[c0 + 0][row] = k0.x; Kt[c0 + 1][row] = k0.y;
            Kt[c0 + 2][row] = k0.z; Kt[c0 + 3][row] = k0.w;
            Kt[c0 + 4][row] = k1.x; Kt[c0 + 5][row] = k1.y;
            Kt[c0 + 6][row] = k1.z; Kt[c0 + 7][row] = k1.w;
            *(float4*)&Vs[row][c0] = *(const float4*)vp;
            *(float4*)&Vs[row][c0 + 4] = *(const float4*)(vp + 4);
        }
        __syncthreads();

        float s0 = 0.f, s1 = 0.f, s2 = 0.f, s3 = 0.f;
#pragma unroll
        for (int d = 0; d < 64; d++) {
            float4 kd = *(const float4*)&Kt[d][g * 4];
            float qd = Qs[r][d];
            s0 = fmaf(qd, kd.x, s0);
            s1 = fmaf(qd, kd.y, s1);
            s2 = fmaf(qd, kd.z, s2);
            s3 = fmaf(qd, kd.w, s3);
        }
        const int jb = jc + g * 4;
        s0 = ((jb + 0) <= i && (i - (jb + 0)) < WIN) ? s0 * 0.125f : -INFINITY;
        s1 = ((jb + 1) <= i && (i - (jb + 1)) < WIN) ? s1 * 0.125f : -INFINITY;
        s2 = ((jb + 2) <= i && (i - (jb + 2)) < WIN) ? s2 * 0.125f : -INFINITY;
        s3 = ((jb + 3) <= i && (i - (jb + 3)) < WIN) ? s3 * 0.125f : -INFINITY;

        float mc = fmaxf(fmaxf(s0, s1), fmaxf(s2, s3));
        mc = fmaxf(mc, __shfl_xor_sync(0xffffffffu, mc, 1));
        mc = fmaxf(mc, __shfl_xor_sync(0xffffffffu, mc, 2));
        mc = fmaxf(mc, __shfl_xor_sync(0xffffffffu, mc, 4));
        float mnew = fmaxf(m, mc);

        float alpha = 1.f;
        float p0 = 0.f, p1 = 0.f, p2 = 0.f, p3 = 0.f;
        if (mnew != -INFINITY) {
            alpha = (m == -INFINITY) ? 0.f : expf(m - mnew);
            p0 = expf(s0 - mnew);
            p1 = expf(s1 - mnew);
            p2 = expf(s2 - mnew);
            p3 = expf(s3 - mnew);
            m = mnew;
        }
        Ps[r][g * 4 + 0] = p0;
        Ps[r][g * 4 + 1] = p1;
        Ps[r][g * 4 + 2] = p2;
        Ps[r][g * 4 + 3] = p3;
        lsum = lsum * alpha + (p0 + p1 + p2 + p3);
        __syncwarp();

#pragma unroll
        for (int d = 0; d < 8; d++) acc[d] *= alpha;
#pragma unroll 4
        for (int j = 0; j < 32; j++) {
            float p = Ps[r][j];
            float4 v0 = *(const float4*)&Vs[j][g * 8];
            float4 v1 = *(const float4*)&Vs[j][g * 8 + 4];
            acc[0] = fmaf(p, v0.x, acc[0]);
            acc[1] = fmaf(p, v0.y, acc[1]);
            acc[2] = fmaf(p, v0.z, acc[2]);
            acc[3] = fmaf(p, v0.w, acc[3]);
            acc[4] = fmaf(p, v1.x, acc[4]);
            acc[5] = fmaf(p, v1.y, acc[5]);
            acc[6] = fmaf(p, v1.z, acc[6]);
            acc[7] = fmaf(p, v1.w, acc[7]);
        }
    }

    float lt = lsum;
    lt += __shfl_xor_sync(0xffffffffu, lt, 1);
    lt += __shfl_xor_sync(0xffffffffu, lt, 2);
    lt += __shfl_xor_sync(0xffffffffu, lt, 4);
    float invl = 1.f / lt;
    size_t ob = (size_t)i * DMODEL + h * HDIM + g * 8;
#pragma unroll
    for (int d = 0; d < 8; d++) {
        float rv = acc[d] * invl;
        if (!isfinite(rv)) rv = 0.f;
        __nv_bfloat16 hb = __float2bfloat16(rv);
        oh[ob + d] = hb;
        ol[ob + d] = __float2bfloat16(rv - __bfloat162float(hb));
    }
}

// ---------------- SwiGLU elementwise -> bf16 hi/lo (padded rows) ----------------
__global__ void swiglu_kernel(const float* __restrict__ z1, const float* __restrict__ z3,
                              __nv_bfloat16* __restrict__ mh, __nv_bfloat16* __restrict__ ml) {
    int idx = blockIdx.x * blockDim.x + threadIdx.x;
    if (idx < LSEQ * KP2) {
        int row = idx / KP2;
        int col = idx - row * KP2;
        float s = 0.f;
        if (col < IDIM) {
            float a = z1[(size_t)row * IDIM + col];
            float b = z3[(size_t)row * IDIM + col];
            s = (a / (1.f + expf(-a))) * b;
        }
        __nv_bfloat16 hb = __float2bfloat16(s);
        mh[idx] = hb;
        ml[idx] = __float2bfloat16(s - __bfloat162float(hb));
    }
}

// ---------------- bf16 split GEMM: mma.sync + cp.async double buffer ----------
// C[m,n] = sum_k A[m,k]*B[n,k] + bias[n];  A = Ah+Al, B = Bh+Bl
// 3 passes (Ah*Bh + Ah*Bl + Al*Bh) into fp32 accumulators.
// grid.x = M-tiles (weight reuse in L2 across a wave), grid.y = N-tiles.
// MODE 0: store, 1: C +=, 2: clip +-50
#define ROWB 80                    // 40 bf16 per smem row (32 data + 8 pad)
#define TILEB (128 * ROWB)         // 10240 bytes per tile
#define GSMEM (2 * 4 * TILEB)      // 81920 bytes: double-buffered 4 tiles

template <int MODE>
__global__ void __launch_bounds__(256, 2)
bgemm_kernel(const __nv_bfloat16* __restrict__ Ah, const __nv_bfloat16* __restrict__ Al,
             const __nv_bfloat16* __restrict__ Bh0, const __nv_bfloat16* __restrict__ Bl0,
             const __nv_bfloat16* __restrict__ Bh1, const __nv_bfloat16* __restrict__ Bl1,
             const __nv_bfloat16* __restrict__ Bh2, const __nv_bfloat16* __restrict__ Bl2,
             const float* __restrict__ b0, const float* __restrict__ b1,
             const float* __restrict__ b2,
             float* __restrict__ C0, float* __restrict__ C1, float* __restrict__ C2,
             int M, int N, int K) {
    const __nv_bfloat16* Bh = (blockIdx.z == 0) ? Bh0 : (blockIdx.z == 1 ? Bh1 : Bh2);
    const __nv_bfloat16* Bl = (blockIdx.z == 0) ? Bl0 : (blockIdx.z == 1 ? Bl1 : Bl2);
    const float* bias = (blockIdx.z == 0) ? b0 : (blockIdx.z == 1 ? b1 : b2);
    float* C = (blockIdx.z == 0) ? C0 : (blockIdx.z == 1 ? C1 : C2);

    extern __shared__ char smem[];
    const uint32_t sb = smem_u32(smem);
    const int tid = threadIdx.x;
    const int wid = tid >> 5;
    const int lane = tid & 31;
    const int bm = blockIdx.x * 128;   // M-tile
    const int bn = blockIdx.y * 128;   // N-tile

    // ---- staging: thread group tgrp handles one of {Ah, Al, Bh, Bl} ----
    const int tgrp = tid >> 6;       // 0..3
    const int tl = tid & 63;
    const int row0 = tl >> 2;        // base row (0..15), +16 per step
    const int ch = tl & 3;           // 16B chunk within row
    const bool isB = tgrp >= 2;
    const __nv_bfloat16* gbase =
        (tgrp == 0) ? Ah : (tgrp == 1) ? Al : (tgrp == 2) ? Bh : Bl;
    const __nv_bfloat16* gsrc = gbase + ch * 8;

    uint32_t offs[8];
#pragma unroll
    for (int c2 = 0; c2 < 8; c2++) {
        int row = row0 + c2 * 16;
        int grow = isB ? min(bn + row, N - 1) : (bm + row);
        offs[c2] = (uint32_t)grow * (uint32_t)K;
    }
    const uint32_t dgrp = sb + (uint32_t)tgrp * TILEB + (uint32_t)ch * 16;

    // ---- fragment setup ----
    float acc[4][4][4];
#pragma unroll
    for (int a = 0; a < 4; a++)
#pragma unroll
        for (int b = 0; b < 4; b++)
#pragma unroll
            for (int c = 0; c < 4; c++) acc[a][b][c] = 0.f;

    const int wm = (wid & 1) * 64;
    const int wn = (wid >> 1) * 32;
    const int lrow = lane & 15;
    const int lcol = lane >> 4;
    const uint32_t offA = (uint32_t)(wm + lrow) * ROWB + (uint32_t)lcol * 16;
    const uint32_t offB = (uint32_t)(wn + lrow) * ROWB + (uint32_t)lcol * 16;

    const int NC = K >> 5;   // K multiple of 32

    // ---- prefetch chunk 0 into buffer 0 ----
#pragma unroll
    for (int c2 = 0; c2 < 8; c2++)
        cpasync16(dgrp + (uint32_t)(row0 + c2 * 16) * ROWB, gsrc + offs[c2]);
    cpcommit();

    for (int c = 0; c < NC; c++) {
        const uint32_t buf = (uint32_t)(c & 1);
        // issue next chunk into other buffer BEFORE waiting (overlap)
        const int nc = c + 1;
        if (nc < NC) {
            const uint32_t db = dgrp + (buf ^ 1u) * 4u * TILEB;
            const int kc = nc * 32;
#pragma unroll
            for (int c2 = 0; c2 < 8; c2++)
                cpasync16(db + (uint32_t)(row0 + c2 * 16) * ROWB, gsrc + offs[c2] + kc);
        }
        cpcommit();
        asm volatile("cp.async.wait_group 1;" ::: "memory");
        __syncthreads();

        const uint32_t tb = sb + buf * 4u * TILEB;
#pragma unroll
        for (int ks = 0; ks < 2; ks++) {
            const uint32_t ko = (uint32_t)ks * 32;
            uint32_t bh[4][2], bl[4][2];
#pragma unroll
            for (int p = 0; p < 2; p++) {
                uint32_t qq[4];
                ldmx4(qq, tb + 2 * TILEB + offB + (uint32_t)p * (16 * ROWB) + ko);
                bh[2 * p][0] = qq[0]; bh[2 * p][1] = qq[2];
                bh[2 * p + 1][0] = qq[1]; bh[2 * p + 1][1] = qq[3];
                ldmx4(qq, tb + 3 * TILEB + offB + (uint32_t)p * (16 * ROWB) + ko);
                bl[2 * p][0] = qq[0]; bl[2 * p][1] = qq[2];
                bl[2 * p + 1][0] = qq[1]; bl[2 * p + 1][1] = qq[3];
            }
#pragma unroll
            for (int mi = 0; mi < 4; mi++) {
                uint32_t ah[4], al[4];
                ldmx4(ah, tb + offA + (uint32_t)mi * (16 * ROWB) + ko);
                ldmx4(al, tb + TILEB + offA + (uint32_t)mi * (16 * ROWB) + ko);
#pragma unroll
                for (int ni = 0; ni < 4; ni++) mma_bf16(acc[mi][ni], ah, bh[ni]);
#pragma unroll
                for (int ni = 0; ni < 4; ni++) mma_bf16(acc[mi][ni], ah, bl[ni]);
#pragma unroll
                for (int ni = 0; ni < 4; ni++) mma_bf16(acc[mi][ni], al, bh[ni]);
            }
        }
        __syncthreads();
    }

    // ---- epilogue ----
#pragma unroll
    for (int mi = 0; mi < 4; mi++) {
        const int r0 = bm + wm + mi * 16 + (lane >> 2);
#pragma unroll
        for (int ni = 0; ni < 4; ni++) {
            const int c0 = bn + wn + ni * 8 + (lane & 3) * 2;
            if (c0 < N) {
                const float bv0 = bias[c0];
                const float bv1 = bias[c0 + 1];
                float* p0 = C + (size_t)r0 * N + c0;
                float* p1 = C + (size_t)(r0 + 8) * N + c0;
                float v00 = acc[mi][ni][0] + bv0;
                float v01 = acc[mi][ni][1] + bv1;
                float v10 = acc[mi][ni][2] + bv0;
                float v11 = acc[mi][ni][3] + bv1;
                if (MODE == 1) {
                    v00 += p0[0]; v01 += p0[1];
                    v10 += p1[0]; v11 += p1[1];
                }
                if (MODE == 2) {
                    v00 = fminf(fmaxf(v00, -50.f), 50.f);
                    v01 = fminf(fmaxf(v01, -50.f), 50.f);
                    v10 = fminf(fmaxf(v10, -50.f), 50.f);
                    v11 = fminf(fmaxf(v11, -50.f), 50.f);
                }
                p0[0] = v00; p0[1] = v01;
                p1[0] = v10; p1[1] = v11;
            }
        }
    }
}

template <int MODE>
static void launch_bgemm(const __nv_bfloat16* Ah, const __nv_bfloat16* Al,
                         const __nv_bfloat16* Bh0, const __nv_bfloat16* Bl0,
                         const __nv_bfloat16* Bh1, const __nv_bfloat16* Bl1,
                         const __nv_bfloat16* Bh2, const __nv_bfloat16* Bl2,
                         const float* b0, const float* b1, const float* b2,
                         float* C0, float* C1, float* C2,
                         int M, int N, int K, int nz) {
    cudaFuncSetAttribute(bgemm_kernel<MODE>, cudaFuncAttributeMaxDynamicSharedMemorySize,
                         GSMEM);
    dim3 grid(M / 128, (N + 127) / 128, nz);
    bgemm_kernel<MODE><<<grid, 256, GSMEM>>>(Ah, Al, Bh0, Bl0, Bh1, Bl1, Bh2, Bl2,
                                             b0, b1, b2, C0, C1, C2, M, N, K);
}

// ---------------- driver ----------------
extern "C" void kernel_launch(void* const* d_in, const int* in_sizes, int n_in,
                              void* d_out, int out_size) {
    const int*   tokens  = (const int*)d_in[0];
    const float* embed_w = (const float*)d_in[1];
    const float* ln1_w   = (const float*)d_in[2];
    const float* ln2_w   = (const float*)d_in[3];
    const float* wq_w    = (const float*)d_in[4];
    const float* wq_b    = (const float*)d_in[5];
    const float* wk_w    = (const float*)d_in[6];
    const float* wk_b    = (const float*)d_in[7];
    const float* wv_w    = (const float*)d_in[8];
    const float* wv_b    = (const float*)d_in[9];
    const float* wo_w    = (const float*)d_in[10];
    const float* wo_b    = (const float*)d_in[11];
    const float* qn_w    = (const float*)d_in[12];
    const float* kn_w    = (const float*)d_in[13];
    const float* w1_w    = (const float*)d_in[14];
    const float* w1_b    = (const float*)d_in[15];
    const float* w2_w    = (const float*)d_in[16];
    const float* w2_b    = (const float*)d_in[17];
    const float* w3_w    = (const float*)d_in[18];
    const float* w3_b    = (const float*)d_in[19];
    const float* lnf_w   = (const float*)d_in[20];
    const float* lm_w    = (const float*)d_in[21];
    const float* lm_b    = (const float*)d_in[22];
    float* out = (float*)d_out;

    float *x, *q, *k, *v, *z1, *z3;
    __nv_bfloat16 *xnh, *xnl, *ah, *al, *mh, *ml;
    __nv_bfloat16 *wqh, *wql, *wkh, *wkl, *wvh, *wvl, *woh, *wol;
    __nv_bfloat16 *w1h, *w1l, *w2h, *w2l, *w3h, *w3l, *lmh, *lml;
    cudaGetSymbolAddress((void**)&x, g_x);
    cudaGetSymbolAddress((void**)&q, g_q);
    cudaGetSymbolAddress((void**)&k, g_k);
    cudaGetSymbolAddress((void**)&v, g_v);
    cudaGetSymbolAddress((void**)&z1, g_z1);
    cudaGetSymbolAddress((void**)&z3, g_z3);
    cudaGetSymbolAddress((void**)&xnh, g_xnh);
    cudaGetSymbolAddress((void**)&xnl, g_xnl);
    cudaGetSymbolAddress((void**)&ah, g_ah);
    cudaGetSymbolAddress((void**)&al, g_al);
    cudaGetSymbolAddress((void**)&mh, g_mh);
    cudaGetSymbolAddress((void**)&ml, g_ml);
    cudaGetSymbolAddress((void**)&wqh, g_wqh);
    cudaGetSymbolAddress((void**)&wql, g_wql);
    cudaGetSymbolAddress((void**)&wkh, g_wkh);
    cudaGetSymbolAddress((void**)&wkl, g_wkl);
    cudaGetSymbolAddress((void**)&wvh, g_wvh);
    cudaGetSymbolAddress((void**)&wvl, g_wvl);
    cudaGetSymbolAddress((void**)&woh, g_woh);
    cudaGetSymbolAddress((void**)&wol, g_wol);
    cudaGetSymbolAddress((void**)&w1h, g_w1h);
    cudaGetSymbolAddress((void**)&w1l, g_w1l);
    cudaGetSymbolAddress((void**)&w2h, g_w2h);
    cudaGetSymbolAddress((void**)&w2l, g_w2l);
    cudaGetSymbolAddress((void**)&w3h, g_w3h);
    cudaGetSymbolAddress((void**)&w3l, g_w3l);
    cudaGetSymbolAddress((void**)&lmh, g_lmh);
    cudaGetSymbolAddress((void**)&lml, g_lml);

    // weight split conversions (w2 gets K-padded layout)
    const int CB = 256;
    conv_hl_kernel<<<(WDD / 4 + CB - 1) / CB, CB>>>(wq_w, wqh, wql, WDD);
    conv_hl_kernel<<<(WDD / 4 + CB - 1) / CB, CB>>>(wk_w, wkh, wkl, WDD);
    conv_hl_kernel<<<(WDD / 4 + CB - 1) / CB, CB>>>(wv_w, wvh, wvl, WDD);
    conv_hl_kernel<<<(WDD / 4 + CB - 1) / CB, CB>>>(wo_w, woh, wol, WDD);
    conv_hl_kernel<<<(WID_ / 4 + CB - 1) / CB, CB>>>(w1_w, w1h, w1l, WID_);
    conv_hl_kernel<<<(WID_ / 4 + CB - 1) / CB, CB>>>(w3_w, w3h, w3l, WID_);
    conv_hl_pad_kernel<<<(WIDP + CB - 1) / CB, CB>>>(w2_w, w2h, w2l, NLYR * DMODEL);
    conv_hl_kernel<<<(WLM / 4 + CB - 1) / CB, CB>>>(lm_w, lmh, lml, WLM);

    embed_kernel<<<LSEQ, 256>>>(tokens, embed_w, x);

    for (int l = 0; l < NLYR; l++) {
        const size_t dd = (size_t)l * DMODEL * DMODEL;
        const size_t db = (size_t)l * DMODEL;
        const size_t di = (size_t)l * IDIM * DMODEL;
        const size_t dip = (size_t)l * DMODEL * KP2;
        const size_t dib = (size_t)l * IDIM;

        rmsnorm_kernel<<<LSEQ, 256>>>(x, ln1_w + db, xnh, xnl);
        launch_bgemm<0>(xnh, xnl,
                        wqh + dd, wql + dd, wkh + dd, wkl + dd, wvh + dd, wvl + dd,
                        wq_b + db, wk_b + db, wv_b + db,
                        q, k, v, LSEQ, DMODEL, DMODEL, 3);
        rmsnorm_head2_kernel<<<dim3((LSEQ * NHEAD) / 8, 2), 256>>>(
            q, k, qn_w + (size_t)l * HDIM, kn_w + (size_t)l * HDIM);
        attn2_kernel<<<dim3(LSEQ / QT, NHEAD), 256>>>(q, k, v, ah, al);
        launch_bgemm<1>(ah, al,
                        woh + dd, wol + dd, woh + dd, wol + dd, woh + dd, wol + dd,
                        wo_b + db, wo_b + db, wo_b + db,
                        x, x, x, LSEQ, DMODEL, DMODEL, 1);

        rmsnorm_kernel<<<LSEQ, 256>>>(x, ln2_w + db, xnh, xnl);
        launch_bgemm<0>(xnh, xnl,
                        w1h + di, w1l + di, w3h + di, w3l + di, w3h + di, w3l + di,
                        w1_b + dib, w3_b + dib, w3_b + dib,
                        z1, z3, z3, LSEQ, IDIM, DMODEL, 2);
        swiglu_kernel<<<(LSEQ * KP2 + 255) / 256, 256>>>(z1, z3, mh, ml);
        launch_bgemm<1>(mh, ml,
                        w2h + dip, w2l + dip, w2h + dip, w2l + dip, w2h + dip, w2l + dip,
                        w2_b + db, w2_b + db, w2_b + db,
                        x, x, x, LSEQ, DMODEL, KP2, 1);
    }

    rmsnorm_kernel<<<LSEQ, 256>>>(x, lnf_w, xnh, xnl);
    launch_bgemm<2>(xnh, xnl,
                    lmh, lml, lmh, lml, lmh, lml,
                    lm_b, lm_b, lm_b,
                    out, out, out, LSEQ, VDIM, DMODEL, 1);
}